// round 1
// baseline (speedup 1.0000x reference)
#include <cuda_runtime.h>
#include <math.h>
#include <math_constants.h>

#define NROW 8192   // B*S
#define DIM  1024
#define SEQ  2048
#define NBATCH 4
#define HID  4096

// ---------------- scratch (static device globals; no runtime alloc) ----------
__device__ float  g_h[(size_t)NROW * DIM];
__device__ float  g_qpre[(size_t)NROW * DIM];
__device__ float  g_kpre[(size_t)NROW * DIM];
__device__ float  g_vpre[(size_t)NROW * DIM];
__device__ float2 g_Qhat[(size_t)NROW * DIM];
__device__ float2 g_Mhat[(size_t)NROW * DIM];   // K̂ -> K̂·V̂ -> cumsum·conj(Q̂)
__device__ float  g_xmid[(size_t)NROW * DIM];
__device__ float  g_h2[(size_t)NROW * DIM];
__device__ float  g_mlp1[(size_t)NROW * HID];
__device__ float2 g_tw[512];

// ---------------- twiddle init ----------------
__global__ void init_tw_kernel() {
    int i = threadIdx.x;  // 512 threads
    double th = -2.0 * CUDART_PI * (double)i / 1024.0;
    g_tw[i] = make_float2((float)cos(th), (float)sin(th));
}

// ---------------- block reduction (sum, sumsq) ----------------
__device__ __forceinline__ float2 block_reduce2(float2 v, float2* sh) {
    int tid = threadIdx.x;
    sh[tid] = v;
    __syncthreads();
    #pragma unroll
    for (int s = 128; s > 0; s >>= 1) {
        if (tid < s) {
            sh[tid].x += sh[tid + s].x;
            sh[tid].y += sh[tid + s].y;
        }
        __syncthreads();
    }
    float2 r = sh[0];
    __syncthreads();
    return r;
}

// ---------------- LayerNorm 1 ----------------
__global__ __launch_bounds__(256) void ln_kernel(
    const float* __restrict__ x, const float* __restrict__ g,
    const float* __restrict__ b, float* __restrict__ out)
{
    __shared__ float2 red[256];
    size_t row = blockIdx.x;
    const float* xp = x + row * DIM;
    float v[4];
    float s = 0.f, ss = 0.f;
    #pragma unroll
    for (int j = 0; j < 4; j++) {
        int idx = threadIdx.x + j * 256;
        v[j] = xp[idx];
        s += v[j]; ss += v[j] * v[j];
    }
    float2 tot = block_reduce2(make_float2(s, ss), red);
    float mu = tot.x * (1.0f / DIM);
    float var = tot.y * (1.0f / DIM) - mu * mu;
    float rstd = rsqrtf(var + 1e-5f);
    float* op = out + row * DIM;
    #pragma unroll
    for (int j = 0; j < 4; j++) {
        int idx = threadIdx.x + j * 256;
        op[idx] = (v[j] - mu) * rstd * g[idx] + b[idx];
    }
}

// ---------------- 1024-pt Stockham FFT in shared memory ----------------
// Forward DFT, natural-order output. 256 threads, 2 butterflies/thread/stage.
__device__ __forceinline__ float2* fft1024(float2* bufA, float2* bufB) {
    float2* x = bufA;
    float2* y = bufB;
    int n = 1024, s = 1;
    #pragma unroll
    for (int st = 0; st < 10; st++) {
        int m = n >> 1;
        __syncthreads();
        #pragma unroll
        for (int j = 0; j < 2; j++) {
            int i = threadIdx.x + j * 256;   // i in [0,512)
            int p = i / s;
            int q = i - p * s;
            float2 w = g_tw[p * s];
            float2 a = x[q + s * p];
            float2 b = x[q + s * (p + m)];
            float2 sum = make_float2(a.x + b.x, a.y + b.y);
            float2 dif = make_float2(a.x - b.x, a.y - b.y);
            y[q + s * (2 * p)]     = sum;
            y[q + s * (2 * p + 1)] = make_float2(dif.x * w.x - dif.y * w.y,
                                                 dif.x * w.y + dif.y * w.x);
        }
        float2* t = x; x = y; y = t;
        n >>= 1; s <<= 1;
    }
    __syncthreads();
    return x;   // after 10 swaps, result back in bufA
}

// ---------------- forward FFT + unit-magnitude normalize ----------------
// mode 0: out = F/|F| ;  mode 1: out *= F/|F| (complex multiply in place)
__global__ __launch_bounds__(256) void fft_norm_kernel(
    const float* __restrict__ in, float2* __restrict__ out, int mode)
{
    __shared__ float2 bufA[1024];
    __shared__ float2 bufB[1024];
    size_t row = blockIdx.x;
    const float* ip = in + row * DIM;
    #pragma unroll
    for (int j = 0; j < 4; j++) {
        int idx = threadIdx.x + j * 256;
        bufA[idx] = make_float2(ip[idx], 0.f);
    }
    float2* res = fft1024(bufA, bufB);
    float2* op = out + row * DIM;
    #pragma unroll
    for (int j = 0; j < 4; j++) {
        int idx = threadIdx.x + j * 256;
        float2 f = res[idx];
        float mag = sqrtf(f.x * f.x + f.y * f.y);
        float inv = 1.0f / fmaxf(mag, 1e-8f);
        f.x *= inv; f.y *= inv;
        if (mode == 0) {
            op[idx] = f;
        } else {
            float2 k = op[idx];
            op[idx] = make_float2(k.x * f.x - k.y * f.y,
                                  k.x * f.y + k.y * f.x);
        }
    }
}

// ---------------- causal prefix sum over sequence, fused * conj(Q̂) --------
__global__ __launch_bounds__(256) void chain_kernel() {
    int gid = blockIdx.x * 256 + threadIdx.x;   // 4096 = NBATCH*DIM
    int b = gid >> 10;
    int bin = gid & 1023;
    size_t base = (size_t)b * SEQ * DIM + bin;
    float2 acc = make_float2(0.f, 0.f);
    #pragma unroll 8
    for (int t = 0; t < SEQ; t++) {
        size_t off = base + (size_t)t * DIM;
        float2 p = g_Mhat[off];
        acc.x += p.x; acc.y += p.y;
        float2 q = g_Qhat[off];
        // acc * conj(q)
        g_Mhat[off] = make_float2(acc.x * q.x + acc.y * q.y,
                                  acc.y * q.x - acc.x * q.y);
    }
}

// ---------------- inverse FFT (conj trick) + residual + LN2 fused ---------
__global__ __launch_bounds__(256) void ifft_res_ln_kernel(
    const float* __restrict__ x, const float* __restrict__ g,
    const float* __restrict__ b)
{
    __shared__ float2 bufA[1024];
    __shared__ float2 bufB[1024];
    size_t row = blockIdx.x;
    const float2* mp = g_Mhat + row * DIM;
    #pragma unroll
    for (int j = 0; j < 4; j++) {
        int idx = threadIdx.x + j * 256;
        float2 m = mp[idx];
        bufA[idx] = make_float2(m.x, -m.y);   // conj
    }
    float2* res = fft1024(bufA, bufB);
    // real(ifft(M)) = real(fft(conj(M))) / N
    const float* xp = x + row * DIM;
    float* xo = g_xmid + row * DIM;
    float xm[4];
    float s = 0.f, ss = 0.f;
    #pragma unroll
    for (int j = 0; j < 4; j++) {
        int idx = threadIdx.x + j * 256;
        float mixed = res[idx].x * (1.0f / 1024.0f);
        float v = xp[idx] + mixed;
        xm[j] = v;
        xo[idx] = v;
        s += v; ss += v * v;
    }
    __syncthreads();   // done reading bufA/bufB before reuse as reduction scratch
    float2 tot = block_reduce2(make_float2(s, ss), bufB);
    float mu = tot.x * (1.0f / DIM);
    float var = tot.y * (1.0f / DIM) - mu * mu;
    float rstd = rsqrtf(var + 1e-5f);
    float* ho = g_h2 + row * DIM;
    #pragma unroll
    for (int j = 0; j < 4; j++) {
        int idx = threadIdx.x + j * 256;
        ho[idx] = (xm[j] - mu) * rstd * g[idx] + b[idx];
    }
}

// ---------------- SGEMM: C = epi(A @ W + bias [, +res]) -------------------
// 128x128 block tile, BK=8, 256 threads, 8x8 register tile, float4 everywhere.
// EPI: 0 = bias only, 1 = bias + exact GELU, 2 = bias + residual add
template<int EPI>
__global__ __launch_bounds__(256) void sgemm_kernel(
    const float* __restrict__ A, const float* __restrict__ W,
    const float* __restrict__ bias, const float* __restrict__ res,
    float* __restrict__ C, int M, int N, int K)
{
    constexpr int BM = 128, BN = 128, BK = 8, TM = 8, TN = 8;
    __shared__ float As[BK][BM];
    __shared__ float Bs[BK][BN];

    int tid = threadIdx.x;
    int bx = blockIdx.x;   // N tiles
    int by = blockIdx.y;   // M tiles

    int aRow = tid >> 1;            // 0..127
    int aCol = (tid & 1) * 4;       // 0 or 4
    int bRow = tid >> 5;            // 0..7
    int bCol = (tid & 31) * 4;      // 0..124

    const float* Ab = A + (size_t)(by * BM) * K;
    const float* Wb = W + bx * BN;

    int tx = tid & 15;
    int ty = tid >> 4;

    float acc[TM][TN];
    #pragma unroll
    for (int i = 0; i < TM; i++)
        #pragma unroll
        for (int j = 0; j < TN; j++) acc[i][j] = 0.f;

    for (int k0 = 0; k0 < K; k0 += BK) {
        float4 a4 = *(const float4*)(Ab + (size_t)aRow * K + k0 + aCol);
        As[aCol + 0][aRow] = a4.x;
        As[aCol + 1][aRow] = a4.y;
        As[aCol + 2][aRow] = a4.z;
        As[aCol + 3][aRow] = a4.w;
        float4 b4 = *(const float4*)(Wb + (size_t)(k0 + bRow) * N + bCol);
        *(float4*)&Bs[bRow][bCol] = b4;
        __syncthreads();

        #pragma unroll
        for (int kk = 0; kk < BK; kk++) {
            float ar[TM], br[TN];
            float4 t0 = *(float4*)&As[kk][ty * TM];
            float4 t1 = *(float4*)&As[kk][ty * TM + 4];
            ar[0]=t0.x; ar[1]=t0.y; ar[2]=t0.z; ar[3]=t0.w;
            ar[4]=t1.x; ar[5]=t1.y; ar[6]=t1.z; ar[7]=t1.w;
            float4 u0 = *(float4*)&Bs[kk][tx * TN];
            float4 u1 = *(float4*)&Bs[kk][tx * TN + 4];
            br[0]=u0.x; br[1]=u0.y; br[2]=u0.z; br[3]=u0.w;
            br[4]=u1.x; br[5]=u1.y; br[6]=u1.z; br[7]=u1.w;
            #pragma unroll
            for (int i = 0; i < TM; i++)
                #pragma unroll
                for (int j = 0; j < TN; j++)
                    acc[i][j] += ar[i] * br[j];
        }
        __syncthreads();
    }

    // epilogue
    #pragma unroll
    for (int i = 0; i < TM; i++) {
        size_t row = (size_t)by * BM + ty * TM + i;
        #pragma unroll
        for (int jq = 0; jq < TN; jq += 4) {
            int colBase = bx * BN + tx * TN + jq;
            float4 o;
            float vv[4];
            #pragma unroll
            for (int j = 0; j < 4; j++) {
                float v = acc[i][jq + j] + bias[colBase + j];
                if (EPI == 1) {
                    v = 0.5f * v * (1.0f + erff(v * 0.70710678118654752f));
                } else if (EPI == 2) {
                    v += res[row * N + colBase + j];
                }
                vv[j] = v;
            }
            o.x = vv[0]; o.y = vv[1]; o.z = vv[2]; o.w = vv[3];
            *(float4*)&C[row * N + colBase] = o;
        }
    }
}

// ---------------- launch ----------------
extern "C" void kernel_launch(void* const* d_in, const int* in_sizes, int n_in,
                              void* d_out, int out_size)
{
    const float* x     = (const float*)d_in[0];
    const float* Wq    = (const float*)d_in[1];
    const float* bq    = (const float*)d_in[2];
    const float* Wk    = (const float*)d_in[3];
    const float* bk    = (const float*)d_in[4];
    const float* Wv    = (const float*)d_in[5];
    const float* bv    = (const float*)d_in[6];
    const float* ln1_g = (const float*)d_in[7];
    const float* ln1_b = (const float*)d_in[8];
    const float* ln2_g = (const float*)d_in[9];
    const float* ln2_b = (const float*)d_in[10];
    const float* W1    = (const float*)d_in[11];
    const float* b1    = (const float*)d_in[12];
    const float* W2    = (const float*)d_in[13];
    const float* b2    = (const float*)d_in[14];
    float* out = (float*)d_out;

    float  *h, *qpre, *kpre, *vpre, *xmid, *h2, *mlp1;
    float2 *Qhat, *Mhat;
    cudaGetSymbolAddress((void**)&h,    g_h);
    cudaGetSymbolAddress((void**)&qpre, g_qpre);
    cudaGetSymbolAddress((void**)&kpre, g_kpre);
    cudaGetSymbolAddress((void**)&vpre, g_vpre);
    cudaGetSymbolAddress((void**)&Qhat, g_Qhat);
    cudaGetSymbolAddress((void**)&Mhat, g_Mhat);
    cudaGetSymbolAddress((void**)&xmid, g_xmid);
    cudaGetSymbolAddress((void**)&h2,   g_h2);
    cudaGetSymbolAddress((void**)&mlp1, g_mlp1);

    init_tw_kernel<<<1, 512>>>();

    // LN1
    ln_kernel<<<NROW, 256>>>(x, ln1_g, ln1_b, h);

    // QKV projections
    dim3 gQKV(DIM / 128, NROW / 128);
    sgemm_kernel<0><<<gQKV, 256>>>(h, Wq, bq, nullptr, qpre, NROW, DIM, DIM);
    sgemm_kernel<0><<<gQKV, 256>>>(h, Wk, bk, nullptr, kpre, NROW, DIM, DIM);
    sgemm_kernel<0><<<gQKV, 256>>>(h, Wv, bv, nullptr, vpre, NROW, DIM, DIM);

    // FFT + unit-magnitude normalization (Fourier-domain unit_projection)
    fft_norm_kernel<<<NROW, 256>>>(qpre, Qhat, 0);
    fft_norm_kernel<<<NROW, 256>>>(kpre, Mhat, 0);   // K̂
    fft_norm_kernel<<<NROW, 256>>>(vpre, Mhat, 1);   // K̂·V̂

    // causal cumsum over sequence in Fourier domain, fused * conj(Q̂)
    chain_kernel<<<(NBATCH * DIM) / 256, 256>>>();

    // inverse FFT + residual + LN2
    ifft_res_ln_kernel<<<NROW, 256>>>(x, ln2_g, ln2_b);

    // MLP
    dim3 gM1(HID / 128, NROW / 128);
    sgemm_kernel<1><<<gM1, 256>>>(h2, W1, b1, nullptr, mlp1, NROW, HID, DIM);
    dim3 gM2(DIM / 128, NROW / 128);
    sgemm_kernel<2><<<gM2, 256>>>(mlp1, W2, b2, xmid, out, NROW, DIM, HID);

    (void)in_sizes; (void)n_in; (void)out_size;
}

// round 4
// speedup vs baseline: 1.7227x; 1.7227x over previous
#include <cuda_runtime.h>
#include <math.h>
#include <math_constants.h>
#include <stdint.h>

#define NROW 8192   // B*S
#define DIM  1024
#define SEQ  2048
#define NBATCH 4
#define HID  4096
#define CHUNKS 16
#define TCHUNK (SEQ / CHUNKS)   // 128

// ---------------- scratch (static device globals; no runtime alloc) ----------
__device__ float  g_h[(size_t)NROW * DIM];
__device__ float  g_qpre[(size_t)NROW * DIM];
__device__ float  g_kpre[(size_t)NROW * DIM];
__device__ float  g_vpre[(size_t)NROW * DIM];
__device__ float2 g_Qhat[(size_t)NROW * DIM];
__device__ float2 g_Mhat[(size_t)NROW * DIM];   // K̂ -> K̂·V̂ -> cumsum·conj(Q̂)
__device__ float  g_xmid[(size_t)NROW * DIM];
__device__ float  g_h2[(size_t)NROW * DIM];
__device__ float  g_mlp1[(size_t)NROW * HID];
__device__ float2 g_tw[512];
__device__ float  g_WqT[(size_t)DIM * DIM];
__device__ float  g_WkT[(size_t)DIM * DIM];
__device__ float  g_WvT[(size_t)DIM * DIM];
__device__ float  g_W1T[(size_t)HID * DIM];   // [4096][1024]
__device__ float  g_W2T[(size_t)DIM * HID];   // [1024][4096]
__device__ float2 g_part[NBATCH * CHUNKS * DIM];

// ---------------- twiddle init ----------------
__global__ void init_tw_kernel() {
    int i = threadIdx.x;  // 512 threads
    double th = -2.0 * CUDART_PI * (double)i / 1024.0;
    g_tw[i] = make_float2((float)cos(th), (float)sin(th));
}

// ---------------- weight transpose (32x32 tiles) ----------------
__global__ __launch_bounds__(256) void transpose_kernel(
    const float* __restrict__ in, float* __restrict__ out, int R, int C)
{
    __shared__ float t[32][33];
    int bx = blockIdx.x, by = blockIdx.y;
    int x = bx * 32 + threadIdx.x;
    int y0 = by * 32 + threadIdx.y;
    #pragma unroll
    for (int j = 0; j < 32; j += 8)
        t[threadIdx.y + j][threadIdx.x] = in[(size_t)(y0 + j) * C + x];
    __syncthreads();
    int ox = by * 32 + threadIdx.x;
    int oy0 = bx * 32 + threadIdx.y;
    #pragma unroll
    for (int j = 0; j < 32; j += 8)
        out[(size_t)(oy0 + j) * R + ox] = t[threadIdx.x][threadIdx.y + j];
}

// ---------------- block reduction (sum, sumsq) ----------------
__device__ __forceinline__ float2 block_reduce2(float2 v, float2* sh) {
    int tid = threadIdx.x;
    sh[tid] = v;
    __syncthreads();
    #pragma unroll
    for (int s = 128; s > 0; s >>= 1) {
        if (tid < s) {
            sh[tid].x += sh[tid + s].x;
            sh[tid].y += sh[tid + s].y;
        }
        __syncthreads();
    }
    float2 r = sh[0];
    __syncthreads();
    return r;
}

// ---------------- LayerNorm 1 ----------------
__global__ __launch_bounds__(256) void ln_kernel(
    const float* __restrict__ x, const float* __restrict__ g,
    const float* __restrict__ b, float* __restrict__ out)
{
    __shared__ float2 red[256];
    size_t row = blockIdx.x;
    const float* xp = x + row * DIM;
    float v[4];
    float s = 0.f, ss = 0.f;
    #pragma unroll
    for (int j = 0; j < 4; j++) {
        int idx = threadIdx.x + j * 256;
        v[j] = xp[idx];
        s += v[j]; ss += v[j] * v[j];
    }
    float2 tot = block_reduce2(make_float2(s, ss), red);
    float mu = tot.x * (1.0f / DIM);
    float var = tot.y * (1.0f / DIM) - mu * mu;
    float rstd = rsqrtf(var + 1e-5f);
    float* op = out + row * DIM;
    #pragma unroll
    for (int j = 0; j < 4; j++) {
        int idx = threadIdx.x + j * 256;
        op[idx] = (v[j] - mu) * rstd * g[idx] + b[idx];
    }
}

// ---------------- 1024-pt Stockham FFT in shared memory ----------------
__device__ __forceinline__ float2* fft1024(float2* bufA, float2* bufB) {
    float2* x = bufA;
    float2* y = bufB;
    int n = 1024, s = 1;
    #pragma unroll
    for (int st = 0; st < 10; st++) {
        int m = n >> 1;
        __syncthreads();
        #pragma unroll
        for (int j = 0; j < 2; j++) {
            int i = threadIdx.x + j * 256;   // i in [0,512)
            int p = i / s;
            int q = i - p * s;
            float2 w = g_tw[p * s];
            float2 a = x[q + s * p];
            float2 b = x[q + s * (p + m)];
            float2 sum = make_float2(a.x + b.x, a.y + b.y);
            float2 dif = make_float2(a.x - b.x, a.y - b.y);
            y[q + s * (2 * p)]     = sum;
            y[q + s * (2 * p + 1)] = make_float2(dif.x * w.x - dif.y * w.y,
                                                 dif.x * w.y + dif.y * w.x);
        }
        float2* t = x; x = y; y = t;
        n >>= 1; s <<= 1;
    }
    __syncthreads();
    return x;
}

// ---------------- forward FFT + unit-magnitude normalize ----------------
__global__ __launch_bounds__(256) void fft_norm_kernel(
    const float* __restrict__ in, float2* __restrict__ out, int mode)
{
    __shared__ float2 bufA[1024];
    __shared__ float2 bufB[1024];
    size_t row = blockIdx.x;
    const float* ip = in + row * DIM;
    #pragma unroll
    for (int j = 0; j < 4; j++) {
        int idx = threadIdx.x + j * 256;
        bufA[idx] = make_float2(ip[idx], 0.f);
    }
    float2* res = fft1024(bufA, bufB);
    float2* op = out + row * DIM;
    #pragma unroll
    for (int j = 0; j < 4; j++) {
        int idx = threadIdx.x + j * 256;
        float2 f = res[idx];
        float mag = sqrtf(f.x * f.x + f.y * f.y);
        float inv = 1.0f / fmaxf(mag, 1e-8f);
        f.x *= inv; f.y *= inv;
        if (mode == 0) {
            op[idx] = f;
        } else {
            float2 k = op[idx];
            op[idx] = make_float2(k.x * f.x - k.y * f.y,
                                  k.x * f.y + k.y * f.x);
        }
    }
}

// ---------------- chain pass A: per-chunk partial sums ----------------
__global__ __launch_bounds__(256) void chain_partial_kernel() {
    int gid = blockIdx.x * 256 + threadIdx.x;   // 65536
    int bin = gid & 1023;
    int chunk = (gid >> 10) & (CHUNKS - 1);
    int b = gid >> 14;
    size_t base = ((size_t)b * SEQ + (size_t)chunk * TCHUNK) * DIM + bin;
    float2 s = make_float2(0.f, 0.f);
    #pragma unroll 4
    for (int i = 0; i < TCHUNK; i++) {
        float2 p = g_Mhat[base + (size_t)i * DIM];
        s.x += p.x; s.y += p.y;
    }
    g_part[gid] = s;
}

// ---------------- chain pass B: scan within chunk + apply conj(Q̂) --------
__global__ __launch_bounds__(256) void chain_apply_kernel() {
    int gid = blockIdx.x * 256 + threadIdx.x;
    int bin = gid & 1023;
    int chunk = (gid >> 10) & (CHUNKS - 1);
    int b = gid >> 14;
    float2 acc = make_float2(0.f, 0.f);
    for (int c = 0; c < chunk; c++) {
        float2 p = g_part[((b * CHUNKS) + c) * 1024 + bin];
        acc.x += p.x; acc.y += p.y;
    }
    size_t base = ((size_t)b * SEQ + (size_t)chunk * TCHUNK) * DIM + bin;
    #pragma unroll 4
    for (int i = 0; i < TCHUNK; i++) {
        size_t off = base + (size_t)i * DIM;
        float2 p = g_Mhat[off];
        acc.x += p.x; acc.y += p.y;
        float2 q = g_Qhat[off];
        g_Mhat[off] = make_float2(acc.x * q.x + acc.y * q.y,
                                  acc.y * q.x - acc.x * q.y);
    }
}

// ---------------- inverse FFT (conj trick) + residual + LN2 fused ---------
__global__ __launch_bounds__(256) void ifft_res_ln_kernel(
    const float* __restrict__ x, const float* __restrict__ g,
    const float* __restrict__ b)
{
    __shared__ float2 bufA[1024];
    __shared__ float2 bufB[1024];
    size_t row = blockIdx.x;
    const float2* mp = g_Mhat + row * DIM;
    #pragma unroll
    for (int j = 0; j < 4; j++) {
        int idx = threadIdx.x + j * 256;
        float2 m = mp[idx];
        bufA[idx] = make_float2(m.x, -m.y);   // conj
    }
    float2* res = fft1024(bufA, bufB);
    const float* xp = x + row * DIM;
    float* xo = g_xmid + row * DIM;
    float xm[4];
    float s = 0.f, ss = 0.f;
    #pragma unroll
    for (int j = 0; j < 4; j++) {
        int idx = threadIdx.x + j * 256;
        float mixed = res[idx].x * (1.0f / 1024.0f);
        float v = xp[idx] + mixed;
        xm[j] = v;
        xo[idx] = v;
        s += v; ss += v * v;
    }
    __syncthreads();
    float2 tot = block_reduce2(make_float2(s, ss), bufB);
    float mu = tot.x * (1.0f / DIM);
    float var = tot.y * (1.0f / DIM) - mu * mu;
    float rstd = rsqrtf(var + 1e-5f);
    float* ho = g_h2 + row * DIM;
    #pragma unroll
    for (int j = 0; j < 4; j++) {
        int idx = threadIdx.x + j * 256;
        ho[idx] = (xm[j] - mu) * rstd * g[idx] + b[idx];
    }
}

// ================== bf16x3 error-compensated mma.sync GEMM ==================
// C[M,N] = epi(A[M,K] @ W[K,N] + bias [, +res]) with WT = W^T ([N,K] row-major).
// 128x128 CTA tile, BK=32, 8 warps (4x2), warp tile 32x64, m16n8k16 bf16 mma.
// Each fp32 operand split x = hi + lo (bf16 each) at tile-fill time; accumulate
// hi*hi + lo*hi + hi*lo in fp32 (missing lo*lo term ~2^-18 relative).
// SMEM tiles: bf16, row stride 40 bf16 (80B) -> conflict-free 4B fragment LDS.
// EPI: 0 = bias, 1 = bias + exact GELU, 2 = bias + residual
#define TILE_U 2560                        // uint32 per tile (128 rows * 20 pairs)
#define SMEM_GEMM (8 * TILE_U * 4)         // 2 stages * 4 tiles * 10KB = 80KB

__device__ __forceinline__ void mma_bf16(float* d, const uint32_t* a, const uint32_t* b) {
    asm volatile("mma.sync.aligned.m16n8k16.row.col.f32.bf16.bf16.f32 "
        "{%0,%1,%2,%3}, {%4,%5,%6,%7}, {%8,%9}, {%0,%1,%2,%3};"
        : "+f"(d[0]), "+f"(d[1]), "+f"(d[2]), "+f"(d[3])
        : "r"(a[0]), "r"(a[1]), "r"(a[2]), "r"(a[3]), "r"(b[0]), "r"(b[1]));
}

// split pair (x0,x1) -> packed bf16x2 hi (low half = x0) and lo
__device__ __forceinline__ void split2(float x0, float x1, uint32_t& hi, uint32_t& lo) {
    uint32_t h;
    asm("cvt.rn.bf16x2.f32 %0, %1, %2;" : "=r"(h) : "f"(x1), "f"(x0));
    float h0 = __uint_as_float(h << 16);
    float h1 = __uint_as_float(h & 0xFFFF0000u);
    float l0 = x0 - h0;
    float l1 = x1 - h1;
    asm("cvt.rn.bf16x2.f32 %0, %1, %2;" : "=r"(lo) : "f"(l1), "f"(l0));
    hi = h;
}

template<int EPI>
__global__ __launch_bounds__(256) void mma_gemm(
    const float* __restrict__ A, const float* __restrict__ WT,
    const float* __restrict__ bias, const float* __restrict__ res,
    float* __restrict__ C, int M, int N, int K)
{
    extern __shared__ uint32_t smu[];
    // layout per stage: [Ahi][Alo][Bhi][Blo], each TILE_U uint32
    uint32_t* Ahi[2] = { smu,              smu + 4 * TILE_U };
    uint32_t* Alo[2] = { smu + TILE_U,     smu + 5 * TILE_U };
    uint32_t* Bhi[2] = { smu + 2 * TILE_U, smu + 6 * TILE_U };
    uint32_t* Blo[2] = { smu + 3 * TILE_U, smu + 7 * TILE_U };

    int tid = threadIdx.x;
    int wid = tid >> 5;
    int lane = tid & 31;
    int wm = wid & 3;        // 0..3 -> 32-row slice
    int wn = wid >> 2;       // 0..1 -> 64-col slice
    int bx = blockIdx.x, by = blockIdx.y;

    const float* Ab = A  + (size_t)by * 128 * K;
    const float* Wb = WT + (size_t)bx * 128 * K;

    // fill assignment: row = tid>>1 (0..127), k-half = (tid&1)*16
    int frow = tid >> 1;
    int fkh  = (tid & 1) * 16;
    const float* apL = Ab + (size_t)frow * K + fkh;
    const float* bpL = Wb + (size_t)frow * K + fkh;
    int pb = frow * 20 + (tid & 1) * 8;    // uint32-pair base offset in tile

    float4 fa[4], fb[4];

    #define LDG_STAGE(k0) do { \
        _Pragma("unroll") \
        for (int q = 0; q < 4; q++) { \
            fa[q] = *(const float4*)(apL + (k0) + q * 4); \
            fb[q] = *(const float4*)(bpL + (k0) + q * 4); \
        } \
    } while (0)

    #define STS_STAGE(s) do { \
        _Pragma("unroll") \
        for (int q = 0; q < 4; q++) { \
            uint32_t h0, l0, h1, l1; \
            split2(fa[q].x, fa[q].y, h0, l0); \
            split2(fa[q].z, fa[q].w, h1, l1); \
            *(uint2*)&Ahi[s][pb + 2 * q] = make_uint2(h0, h1); \
            *(uint2*)&Alo[s][pb + 2 * q] = make_uint2(l0, l1); \
            split2(fb[q].x, fb[q].y, h0, l0); \
            split2(fb[q].z, fb[q].w, h1, l1); \
            *(uint2*)&Bhi[s][pb + 2 * q] = make_uint2(h0, h1); \
            *(uint2*)&Blo[s][pb + 2 * q] = make_uint2(l0, l1); \
        } \
    } while (0)

    float acc[2][8][4];
    #pragma unroll
    for (int mt = 0; mt < 2; mt++)
        #pragma unroll
        for (int nt = 0; nt < 8; nt++)
            #pragma unroll
            for (int i = 0; i < 4; i++) acc[mt][nt][i] = 0.f;

    int KT = K >> 5;

    // prologue: stage0 -> SMEM, stage1 -> regs
    LDG_STAGE(0);
    STS_STAGE(0);
    if (KT > 1) LDG_STAGE(32);
    __syncthreads();

    int gq = lane >> 2, tq = lane & 3;
    int aBase0 = (wm * 32 + gq) * 20 + tq;
    int bBase0 = (wn * 64 + gq) * 20 + tq;

    for (int it = 0; it < KT; it++) {
        int s = it & 1;
        if (it + 1 < KT) {
            STS_STAGE(s ^ 1);
            if (it + 2 < KT) LDG_STAGE((it + 2) * 32);
            __syncthreads();
        }

        const uint32_t* ah_t = Ahi[s];
        const uint32_t* al_t = Alo[s];
        const uint32_t* bh_t = Bhi[s];
        const uint32_t* bl_t = Blo[s];

        #pragma unroll
        for (int ks = 0; ks < 2; ks++) {
            int ko = ks * 8;
            uint32_t ah[2][4], al[2][4], bb[8][2];
            #pragma unroll
            for (int mt = 0; mt < 2; mt++) {
                int base = aBase0 + mt * 320 + ko;
                ah[mt][0] = ah_t[base];
                ah[mt][1] = ah_t[base + 160];
                ah[mt][2] = ah_t[base + 4];
                ah[mt][3] = ah_t[base + 164];
                al[mt][0] = al_t[base];
                al[mt][1] = al_t[base + 160];
                al[mt][2] = al_t[base + 4];
                al[mt][3] = al_t[base + 164];
            }
            #pragma unroll
            for (int nt = 0; nt < 8; nt++) {
                int base = bBase0 + nt * 160 + ko;
                bb[nt][0] = bh_t[base];
                bb[nt][1] = bh_t[base + 4];
            }
            // pass 1: hi*hi ; pass 2: lo*hi
            #pragma unroll
            for (int mt = 0; mt < 2; mt++)
                #pragma unroll
                for (int nt = 0; nt < 8; nt++) {
                    mma_bf16(acc[mt][nt], ah[mt], bb[nt]);
                    mma_bf16(acc[mt][nt], al[mt], bb[nt]);
                }
            // pass 3: hi*lo
            #pragma unroll
            for (int nt = 0; nt < 8; nt++) {
                int base = bBase0 + nt * 160 + ko;
                bb[nt][0] = bl_t[base];
                bb[nt][1] = bl_t[base + 4];
            }
            #pragma unroll
            for (int mt = 0; mt < 2; mt++)
                #pragma unroll
                for (int nt = 0; nt < 8; nt++)
                    mma_bf16(acc[mt][nt], ah[mt], bb[nt]);
        }
        __syncthreads();
    }

    // ---- epilogue ----
    #pragma unroll
    for (int mt = 0; mt < 2; mt++) {
        #pragma unroll
        for (int nt = 0; nt < 8; nt++) {
            int r0 = by * 128 + wm * 32 + mt * 16 + gq;
            int c0 = bx * 128 + wn * 64 + nt * 8 + tq * 2;
            float b0 = bias[c0], b1 = bias[c0 + 1];
            #pragma unroll
            for (int half = 0; half < 2; half++) {
                int r = r0 + half * 8;
                float v0 = acc[mt][nt][half * 2 + 0] + b0;
                float v1 = acc[mt][nt][half * 2 + 1] + b1;
                if (EPI == 1) {
                    v0 = 0.5f * v0 * (1.0f + erff(v0 * 0.70710678118654752f));
                    v1 = 0.5f * v1 * (1.0f + erff(v1 * 0.70710678118654752f));
                } else if (EPI == 2) {
                    float2 rv = *(const float2*)(res + (size_t)r * N + c0);
                    v0 += rv.x; v1 += rv.y;
                }
                float2 o; o.x = v0; o.y = v1;
                *(float2*)(C + (size_t)r * N + c0) = o;
            }
        }
    }
    (void)M;
}

// ---------------- launch ----------------
extern "C" void kernel_launch(void* const* d_in, const int* in_sizes, int n_in,
                              void* d_out, int out_size)
{
    const float* x     = (const float*)d_in[0];
    const float* Wq    = (const float*)d_in[1];
    const float* bq    = (const float*)d_in[2];
    const float* Wk    = (const float*)d_in[3];
    const float* bk    = (const float*)d_in[4];
    const float* Wv    = (const float*)d_in[5];
    const float* bv    = (const float*)d_in[6];
    const float* ln1_g = (const float*)d_in[7];
    const float* ln1_b = (const float*)d_in[8];
    const float* ln2_g = (const float*)d_in[9];
    const float* ln2_b = (const float*)d_in[10];
    const float* W1    = (const float*)d_in[11];
    const float* b1    = (const float*)d_in[12];
    const float* W2    = (const float*)d_in[13];
    const float* b2    = (const float*)d_in[14];
    float* out = (float*)d_out;

    float  *h, *qpre, *kpre, *vpre, *xmid, *h2, *mlp1;
    float  *WqT, *WkT, *WvT, *W1T, *W2T;
    float2 *Qhat, *Mhat;
    cudaGetSymbolAddress((void**)&h,    g_h);
    cudaGetSymbolAddress((void**)&qpre, g_qpre);
    cudaGetSymbolAddress((void**)&kpre, g_kpre);
    cudaGetSymbolAddress((void**)&vpre, g_vpre);
    cudaGetSymbolAddress((void**)&Qhat, g_Qhat);
    cudaGetSymbolAddress((void**)&Mhat, g_Mhat);
    cudaGetSymbolAddress((void**)&xmid, g_xmid);
    cudaGetSymbolAddress((void**)&h2,   g_h2);
    cudaGetSymbolAddress((void**)&mlp1, g_mlp1);
    cudaGetSymbolAddress((void**)&WqT,  g_WqT);
    cudaGetSymbolAddress((void**)&WkT,  g_WkT);
    cudaGetSymbolAddress((void**)&WvT,  g_WvT);
    cudaGetSymbolAddress((void**)&W1T,  g_W1T);
    cudaGetSymbolAddress((void**)&W2T,  g_W2T);

    cudaFuncSetAttribute(mma_gemm<0>, cudaFuncAttributeMaxDynamicSharedMemorySize, SMEM_GEMM);
    cudaFuncSetAttribute(mma_gemm<1>, cudaFuncAttributeMaxDynamicSharedMemorySize, SMEM_GEMM);
    cudaFuncSetAttribute(mma_gemm<2>, cudaFuncAttributeMaxDynamicSharedMemorySize, SMEM_GEMM);

    init_tw_kernel<<<1, 512>>>();

    // transpose weights: in [K][N] -> out [N][K]
    transpose_kernel<<<dim3(DIM / 32, DIM / 32), dim3(32, 8)>>>(Wq, WqT, DIM, DIM);
    transpose_kernel<<<dim3(DIM / 32, DIM / 32), dim3(32, 8)>>>(Wk, WkT, DIM, DIM);
    transpose_kernel<<<dim3(DIM / 32, DIM / 32), dim3(32, 8)>>>(Wv, WvT, DIM, DIM);
    transpose_kernel<<<dim3(HID / 32, DIM / 32), dim3(32, 8)>>>(W1, W1T, DIM, HID);
    transpose_kernel<<<dim3(DIM / 32, HID / 32), dim3(32, 8)>>>(W2, W2T, HID, DIM);

    // LN1
    ln_kernel<<<NROW, 256>>>(x, ln1_g, ln1_b, h);

    // QKV projections (bf16x3 tensor-core mma.sync)
    dim3 gQKV(DIM / 128, NROW / 128);
    mma_gemm<0><<<gQKV, 256, SMEM_GEMM>>>(h, WqT, bq, nullptr, qpre, NROW, DIM, DIM);
    mma_gemm<0><<<gQKV, 256, SMEM_GEMM>>>(h, WkT, bk, nullptr, kpre, NROW, DIM, DIM);
    mma_gemm<0><<<gQKV, 256, SMEM_GEMM>>>(h, WvT, bv, nullptr, vpre, NROW, DIM, DIM);

    // FFT + unit-magnitude normalization
    fft_norm_kernel<<<NROW, 256>>>(qpre, Qhat, 0);
    fft_norm_kernel<<<NROW, 256>>>(kpre, Mhat, 0);   // K̂
    fft_norm_kernel<<<NROW, 256>>>(vpre, Mhat, 1);   // K̂·V̂

    // causal cumsum in Fourier domain (2-pass chunked scan), fused * conj(Q̂)
    chain_partial_kernel<<<(NBATCH * CHUNKS * DIM) / 256, 256>>>();
    chain_apply_kernel<<<(NBATCH * CHUNKS * DIM) / 256, 256>>>();

    // inverse FFT + residual + LN2
    ifft_res_ln_kernel<<<NROW, 256>>>(x, ln2_g, ln2_b);

    // MLP
    mma_gemm<1><<<dim3(HID / 128, NROW / 128), 256, SMEM_GEMM>>>(h2, W1T, b1, nullptr, mlp1, NROW, HID, DIM);
    mma_gemm<2><<<dim3(DIM / 128, NROW / 128), 256, SMEM_GEMM>>>(mlp1, W2T, b2, xmid, out, NROW, DIM, HID);

    (void)in_sizes; (void)n_in; (void)out_size;
}

// round 5
// speedup vs baseline: 2.0897x; 1.2130x over previous
#include <cuda_runtime.h>
#include <math.h>
#include <math_constants.h>
#include <stdint.h>

#define NROW 8192   // B*S
#define DIM  1024
#define SEQ  2048
#define NBATCH 4
#define HID  4096
#define CHUNKS 16
#define TCHUNK (SEQ / CHUNKS)   // 128
#define NQKV 3072

// ---------------- scratch (static device globals; no runtime alloc) ----------
__device__ uint16_t g_h_hi[(size_t)NROW * DIM];
__device__ uint16_t g_h_lo[(size_t)NROW * DIM];
__device__ uint16_t g_h2_hi[(size_t)NROW * DIM];
__device__ uint16_t g_h2_lo[(size_t)NROW * DIM];
__device__ uint16_t g_m1_hi[(size_t)NROW * HID];
__device__ uint16_t g_m1_lo[(size_t)NROW * HID];
__device__ uint16_t g_Wqkv_hi[(size_t)NQKV * DIM];
__device__ uint16_t g_Wqkv_lo[(size_t)NQKV * DIM];
__device__ uint16_t g_W1_hi[(size_t)HID * DIM];
__device__ uint16_t g_W1_lo[(size_t)HID * DIM];
__device__ uint16_t g_W2_hi[(size_t)DIM * HID];
__device__ uint16_t g_W2_lo[(size_t)DIM * HID];
__device__ float  g_qkv[(size_t)NROW * NQKV];
__device__ float  g_bqkv[NQKV];
__device__ float2 g_Qhat[(size_t)NROW * DIM];
__device__ float2 g_Mhat[(size_t)NROW * DIM];
__device__ float  g_xmid[(size_t)NROW * DIM];
__device__ float2 g_tw[512];
__device__ float2 g_part[NBATCH * CHUNKS * DIM];

// ---------------- helpers ----------------
__device__ __forceinline__ uint32_t smem_u32(const void* p) {
    uint32_t a;
    asm("{ .reg .u64 t; cvta.to.shared.u64 t, %1; cvt.u32.u64 %0, t; }" : "=r"(a) : "l"(p));
    return a;
}
// split pair (x0,x1) -> packed bf16x2 hi (low half = x0) and lo
__device__ __forceinline__ void split2(float x0, float x1, uint32_t& hi, uint32_t& lo) {
    uint32_t h;
    asm("cvt.rn.bf16x2.f32 %0, %1, %2;" : "=r"(h) : "f"(x1), "f"(x0));
    float h0 = __uint_as_float(h << 16);
    float h1 = __uint_as_float(h & 0xFFFF0000u);
    float l0 = x0 - h0;
    float l1 = x1 - h1;
    asm("cvt.rn.bf16x2.f32 %0, %1, %2;" : "=r"(lo) : "f"(l1), "f"(l0));
    hi = h;
}
__device__ __forceinline__ void mma_bf16(float* d, const uint32_t* a, const uint32_t* b) {
    asm volatile("mma.sync.aligned.m16n8k16.row.col.f32.bf16.bf16.f32 "
        "{%0,%1,%2,%3}, {%4,%5,%6,%7}, {%8,%9}, {%0,%1,%2,%3};"
        : "+f"(d[0]), "+f"(d[1]), "+f"(d[2]), "+f"(d[3])
        : "r"(a[0]), "r"(a[1]), "r"(a[2]), "r"(a[3]), "r"(b[0]), "r"(b[1]));
}
__device__ __forceinline__ void cpa16(uint32_t dst, const void* src) {
    asm volatile("cp.async.cg.shared.global [%0], [%1], 16;" :: "r"(dst), "l"(src) : "memory");
}

// ---------------- twiddle init ----------------
__global__ void init_tw_kernel() {
    int i = threadIdx.x;
    double th = -2.0 * CUDART_PI * (double)i / 1024.0;
    g_tw[i] = make_float2((float)cos(th), (float)sin(th));
}

// ---------------- bias concat ----------------
__global__ void bias_concat_kernel(const float* bq, const float* bk, const float* bv) {
    int i = blockIdx.x * 256 + threadIdx.x;
    float v = (i < 1024) ? bq[i] : (i < 2048) ? bk[i - 1024] : bv[i - 2048];
    g_bqkv[i] = v;
}

// ---------------- weight transpose + bf16 split ----------------
// in: W [R(=K)][C(=N)] fp32 row-major.  out: WT planes [N][K] bf16 hi/lo.
__global__ __launch_bounds__(256) void transpose_split_kernel(
    const float* __restrict__ in, uint16_t* __restrict__ ohi,
    uint16_t* __restrict__ olo, int R, int C)
{
    __shared__ float t[32][33];
    int bx = blockIdx.x, by = blockIdx.y;
    int x = bx * 32 + threadIdx.x;
    int y0 = by * 32 + threadIdx.y;
    #pragma unroll
    for (int j = 0; j < 32; j += 8)
        t[threadIdx.y + j][threadIdx.x] = in[(size_t)(y0 + j) * C + x];
    __syncthreads();
    int tl = threadIdx.y * 32 + threadIdx.x;   // 0..255
    int kp = tl & 15;                           // k pair 0..15
    int nr0 = tl >> 4;                          // 0..15
    uint32_t* hw32 = (uint32_t*)ohi;
    uint32_t* lw32 = (uint32_t*)olo;
    #pragma unroll
    for (int rep = 0; rep < 2; rep++) {
        int nrel = nr0 + rep * 16;
        size_t n = (size_t)bx * 32 + nrel;
        int kg = by * 32 + kp * 2;
        uint32_t hw, lw;
        split2(t[kp * 2][nrel], t[kp * 2 + 1][nrel], hw, lw);
        size_t widx = (n * (size_t)R + kg) >> 1;
        hw32[widx] = hw;
        lw32[widx] = lw;
    }
}

// ---------------- block reduction ----------------
__device__ __forceinline__ float2 block_reduce2(float2 v, float2* sh) {
    int tid = threadIdx.x;
    sh[tid] = v;
    __syncthreads();
    #pragma unroll
    for (int s = 128; s > 0; s >>= 1) {
        if (tid < s) {
            sh[tid].x += sh[tid + s].x;
            sh[tid].y += sh[tid + s].y;
        }
        __syncthreads();
    }
    float2 r = sh[0];
    __syncthreads();
    return r;
}

// ---------------- LayerNorm 1 -> bf16 hi/lo planes ----------------
__global__ __launch_bounds__(256) void ln_split_kernel(
    const float* __restrict__ x, const float* __restrict__ g,
    const float* __restrict__ b, uint16_t* __restrict__ ohi,
    uint16_t* __restrict__ olo)
{
    __shared__ float2 red[256];
    size_t row = blockIdx.x;
    int tid = threadIdx.x;
    float4 v = ((const float4*)(x + row * DIM))[tid];
    float s = v.x + v.y + v.z + v.w;
    float ss = v.x * v.x + v.y * v.y + v.z * v.z + v.w * v.w;
    float2 tot = block_reduce2(make_float2(s, ss), red);
    float mu = tot.x * (1.0f / DIM);
    float var = tot.y * (1.0f / DIM) - mu * mu;
    float rstd = rsqrtf(var + 1e-5f);
    float4 gg = ((const float4*)g)[tid];
    float4 bb = ((const float4*)b)[tid];
    float y0 = (v.x - mu) * rstd * gg.x + bb.x;
    float y1 = (v.y - mu) * rstd * gg.y + bb.y;
    float y2 = (v.z - mu) * rstd * gg.z + bb.z;
    float y3 = (v.w - mu) * rstd * gg.w + bb.w;
    uint32_t h0, l0, h1, l1;
    split2(y0, y1, h0, l0);
    split2(y2, y3, h1, l1);
    uint32_t* hw = (uint32_t*)ohi;
    uint32_t* lw = (uint32_t*)olo;
    size_t wb = row * 512 + tid * 2;
    hw[wb] = h0; hw[wb + 1] = h1;
    lw[wb] = l0; lw[wb + 1] = l1;
}

// ---------------- 1024-pt Stockham FFT in shared memory ----------------
__device__ __forceinline__ float2* fft1024(float2* bufA, float2* bufB) {
    float2* x = bufA;
    float2* y = bufB;
    int n = 1024, s = 1;
    #pragma unroll
    for (int st = 0; st < 10; st++) {
        int m = n >> 1;
        __syncthreads();
        #pragma unroll
        for (int j = 0; j < 2; j++) {
            int i = threadIdx.x + j * 256;
            int p = i / s;
            int q = i - p * s;
            float2 w = g_tw[p * s];
            float2 a = x[q + s * p];
            float2 b = x[q + s * (p + m)];
            float2 sum = make_float2(a.x + b.x, a.y + b.y);
            float2 dif = make_float2(a.x - b.x, a.y - b.y);
            y[q + s * (2 * p)]     = sum;
            y[q + s * (2 * p + 1)] = make_float2(dif.x * w.x - dif.y * w.y,
                                                 dif.x * w.y + dif.y * w.x);
        }
        float2* t = x; x = y; y = t;
        n >>= 1; s <<= 1;
    }
    __syncthreads();
    return x;
}

// ---------------- forward FFT + unit-magnitude normalize ----------------
__global__ __launch_bounds__(256) void fft_norm_kernel(
    const float* __restrict__ in, int istride, int ioff,
    float2* __restrict__ out, int mode)
{
    __shared__ __align__(16) float2 bufA[1024];
    __shared__ __align__(16) float2 bufB[1024];
    size_t row = blockIdx.x;
    const float* ip = in + row * istride + ioff;
    #pragma unroll
    for (int j = 0; j < 4; j++) {
        int idx = threadIdx.x + j * 256;
        bufA[idx] = make_float2(ip[idx], 0.f);
    }
    float2* res = fft1024(bufA, bufB);
    float2* op = out + row * DIM;
    #pragma unroll
    for (int j = 0; j < 4; j++) {
        int idx = threadIdx.x + j * 256;
        float2 f = res[idx];
        float mag = sqrtf(f.x * f.x + f.y * f.y);
        float inv = 1.0f / fmaxf(mag, 1e-8f);
        f.x *= inv; f.y *= inv;
        if (mode == 0) {
            op[idx] = f;
        } else {
            float2 k = op[idx];
            op[idx] = make_float2(k.x * f.x - k.y * f.y,
                                  k.x * f.y + k.y * f.x);
        }
    }
}

// ---------------- chain pass A: per-chunk partial sums ----------------
__global__ __launch_bounds__(256) void chain_partial_kernel() {
    int gid = blockIdx.x * 256 + threadIdx.x;
    int bin = gid & 1023;
    int chunk = (gid >> 10) & (CHUNKS - 1);
    int b = gid >> 14;
    size_t base = ((size_t)b * SEQ + (size_t)chunk * TCHUNK) * DIM + bin;
    float2 s = make_float2(0.f, 0.f);
    #pragma unroll 4
    for (int i = 0; i < TCHUNK; i++) {
        float2 p = g_Mhat[base + (size_t)i * DIM];
        s.x += p.x; s.y += p.y;
    }
    g_part[gid] = s;
}

// ---------------- chain pass B: scan within chunk + apply conj(Q̂) --------
__global__ __launch_bounds__(256) void chain_apply_kernel() {
    int gid = blockIdx.x * 256 + threadIdx.x;
    int bin = gid & 1023;
    int chunk = (gid >> 10) & (CHUNKS - 1);
    int b = gid >> 14;
    float2 acc = make_float2(0.f, 0.f);
    for (int c = 0; c < chunk; c++) {
        float2 p = g_part[((b * CHUNKS) + c) * 1024 + bin];
        acc.x += p.x; acc.y += p.y;
    }
    size_t base = ((size_t)b * SEQ + (size_t)chunk * TCHUNK) * DIM + bin;
    #pragma unroll 4
    for (int i = 0; i < TCHUNK; i++) {
        size_t off = base + (size_t)i * DIM;
        float2 p = g_Mhat[off];
        acc.x += p.x; acc.y += p.y;
        float2 q = g_Qhat[off];
        g_Mhat[off] = make_float2(acc.x * q.x + acc.y * q.y,
                                  acc.y * q.x - acc.x * q.y);
    }
}

// ------- inverse FFT + residual + LN2, emits xmid fp32 and h2 bf16 planes ----
__global__ __launch_bounds__(256) void ifft_res_ln_split_kernel(
    const float* __restrict__ x, const float* __restrict__ g,
    const float* __restrict__ b, uint16_t* __restrict__ ohi,
    uint16_t* __restrict__ olo)
{
    __shared__ __align__(16) float2 bufA[1024];
    __shared__ __align__(16) float2 bufB[1024];
    size_t row = blockIdx.x;
    int tid = threadIdx.x;
    const float2* mp = g_Mhat + row * DIM;
    #pragma unroll
    for (int j = 0; j < 4; j++) {
        int idx = tid + j * 256;
        float2 m = mp[idx];
        bufA[idx] = make_float2(m.x, -m.y);
    }
    float2* res = fft1024(bufA, bufB);
    float mixed[4];
    #pragma unroll
    for (int j = 0; j < 4; j++) mixed[j] = res[tid + j * 256].x * (1.0f / 1024.0f);
    __syncthreads();   // all reads of bufA complete before float reuse
    float* sbuf = (float*)bufA;
    const float* xp = x + row * DIM;
    float* xo = g_xmid + row * DIM;
    float s = 0.f, ss = 0.f;
    #pragma unroll
    for (int j = 0; j < 4; j++) {
        int idx = tid + j * 256;
        float v = xp[idx] + mixed[j];
        xo[idx] = v;
        sbuf[idx] = v;
        s += v; ss += v * v;
    }
    float2 tot = block_reduce2(make_float2(s, ss), bufB);  // syncs make sbuf visible
    float mu = tot.x * (1.0f / DIM);
    float var = tot.y * (1.0f / DIM) - mu * mu;
    float rstd = rsqrtf(var + 1e-5f);
    float4 vv = ((const float4*)sbuf)[tid];
    float4 gg = ((const float4*)g)[tid];
    float4 bb = ((const float4*)b)[tid];
    float y0 = (vv.x - mu) * rstd * gg.x + bb.x;
    float y1 = (vv.y - mu) * rstd * gg.y + bb.y;
    float y2 = (vv.z - mu) * rstd * gg.z + bb.z;
    float y3 = (vv.w - mu) * rstd * gg.w + bb.w;
    uint32_t h0, l0, h1, l1;
    split2(y0, y1, h0, l0);
    split2(y2, y3, h1, l1);
    uint32_t* hw = (uint32_t*)ohi;
    uint32_t* lw = (uint32_t*)olo;
    size_t wb = row * 512 + tid * 2;
    hw[wb] = h0; hw[wb + 1] = h1;
    lw[wb] = l0; lw[wb + 1] = l1;
}

// ================== bf16x3 mma.sync GEMM, pre-split planes ==================
// 128x128 CTA tile, BK=32, 4 warps (2x2), warp tile 64x64, 2-stage cp.async.
// SMEM per stage: Ahi|Alo|Bhi|Blo, each 128 rows x 40 bf16 (stride 20 words).
// EPI: 0 = bias -> Cf ; 1 = bias + GELU -> Chi/Clo planes ; 2 = bias+res -> Cf
#define PLANE_W 2560u                     // words per plane
#define STAGE_B 40960u                    // bytes per stage (4 planes)
#define SMEM_GEMM (2 * STAGE_B)           // 81920

template<int EPI>
__global__ __launch_bounds__(128) void mma_gemm(
    const uint16_t* __restrict__ Ahi, const uint16_t* __restrict__ Alo,
    const uint16_t* __restrict__ Bhi, const uint16_t* __restrict__ Blo,
    const float* __restrict__ bias, const float* __restrict__ res,
    float* __restrict__ Cf, uint32_t* __restrict__ Chi, uint32_t* __restrict__ Clo,
    int N, int K)
{
    extern __shared__ uint32_t smu[];
    uint32_t su = smem_u32(smu);

    int tid = threadIdx.x;
    int wid = tid >> 5;
    int lane = tid & 31;
    int wm = wid & 1;
    int wn = wid >> 1;
    int bx = blockIdx.x, by = blockIdx.y;
    int gq = lane >> 2, tq = lane & 3;

    int frow = tid;   // 0..127
    const uint16_t* aH = Ahi + (size_t)(by * 128 + frow) * K;
    const uint16_t* aL = Alo + (size_t)(by * 128 + frow) * K;
    const uint16_t* bH = Bhi + (size_t)(bx * 128 + frow) * K;
    const uint16_t* bL = Blo + (size_t)(bx * 128 + frow) * K;

    #define LOAD_STAGE(s, k0) do { \
        uint32_t _d = su + (uint32_t)(s) * STAGE_B + (uint32_t)frow * 80u; \
        _Pragma("unroll") \
        for (int c = 0; c < 4; c++) { \
            cpa16(_d + c * 16,          aH + (k0) + c * 8); \
            cpa16(_d + 10240 + c * 16,  aL + (k0) + c * 8); \
            cpa16(_d + 20480 + c * 16,  bH + (k0) + c * 8); \
            cpa16(_d + 30720 + c * 16,  bL + (k0) + c * 8); \
        } \
        asm volatile("cp.async.commit_group;" ::: "memory"); \
    } while (0)

    float acc[4][8][4];
    #pragma unroll
    for (int mt = 0; mt < 4; mt++)
        #pragma unroll
        for (int nt = 0; nt < 8; nt++)
            #pragma unroll
            for (int i = 0; i < 4; i++) acc[mt][nt][i] = 0.f;

    int KT = K >> 5;
    LOAD_STAGE(0, 0);

    int aBase0 = (wm * 64 + gq) * 20 + tq;
    int bBase0 = (wn * 64 + gq) * 20 + tq;

    for (int it = 0; it < KT; it++) {
        asm volatile("cp.async.wait_group 0;" ::: "memory");
        __syncthreads();
        if (it + 1 < KT) LOAD_STAGE((it + 1) & 1, (it + 1) * 32);

        int s = it & 1;
        const uint32_t* ah_t = smu + s * 10240;
        const uint32_t* al_t = ah_t + PLANE_W;
        const uint32_t* bh_t = ah_t + 2 * PLANE_W;
        const uint32_t* bl_t = ah_t + 3 * PLANE_W;

        #pragma unroll
        for (int ks = 0; ks < 2; ks++) {
            int ko = ks * 8;
            uint32_t ah[4][4], al[4][4], bb[8][2];
            #pragma unroll
            for (int mt = 0; mt < 4; mt++) {
                int base = aBase0 + mt * 320 + ko;
                ah[mt][0] = ah_t[base];
                ah[mt][1] = ah_t[base + 160];
                ah[mt][2] = ah_t[base + 4];
                ah[mt][3] = ah_t[base + 164];
                al[mt][0] = al_t[base];
                al[mt][1] = al_t[base + 160];
                al[mt][2] = al_t[base + 4];
                al[mt][3] = al_t[base + 164];
            }
            #pragma unroll
            for (int nt = 0; nt < 8; nt++) {
                int base = bBase0 + nt * 160 + ko;
                bb[nt][0] = bh_t[base];
                bb[nt][1] = bh_t[base + 4];
            }
            #pragma unroll
            for (int mt = 0; mt < 4; mt++)
                #pragma unroll
                for (int nt = 0; nt < 8; nt++) {
                    mma_bf16(acc[mt][nt], ah[mt], bb[nt]);
                    mma_bf16(acc[mt][nt], al[mt], bb[nt]);
                }
            #pragma unroll
            for (int nt = 0; nt < 8; nt++) {
                int base = bBase0 + nt * 160 + ko;
                bb[nt][0] = bl_t[base];
                bb[nt][1] = bl_t[base + 4];
            }
            #pragma unroll
            for (int mt = 0; mt < 4; mt++)
                #pragma unroll
                for (int nt = 0; nt < 8; nt++)
                    mma_bf16(acc[mt][nt], ah[mt], bb[nt]);
        }
        __syncthreads();
    }

    // ---- epilogue ----
    #pragma unroll
    for (int mt = 0; mt < 4; mt++) {
        #pragma unroll
        for (int nt = 0; nt < 8; nt++) {
            int r0 = by * 128 + wm * 64 + mt * 16 + gq;
            int c0 = bx * 128 + wn * 64 + nt * 8 + tq * 2;
            float b0 = bias[c0], b1 = bias[c0 + 1];
            #pragma unroll
            for (int half = 0; half < 2; half++) {
                size_t r = r0 + half * 8;
                float v0 = acc[mt][nt][half * 2 + 0] + b0;
                float v1 = acc[mt][nt][half * 2 + 1] + b1;
                if (EPI == 1) {
                    v0 = 0.5f * v0 * (1.0f + erff(v0 * 0.70710678118654752f));
                    v1 = 0.5f * v1 * (1.0f + erff(v1 * 0.70710678118654752f));
                    uint32_t hw, lw;
                    split2(v0, v1, hw, lw);
                    size_t widx = (r * (size_t)N + c0) >> 1;
                    Chi[widx] = hw;
                    Clo[widx] = lw;
                } else {
                    if (EPI == 2) {
                        float2 rv = *(const float2*)(res + r * (size_t)N + c0);
                        v0 += rv.x; v1 += rv.y;
                    }
                    float2 o; o.x = v0; o.y = v1;
                    *(float2*)(Cf + r * (size_t)N + c0) = o;
                }
            }
        }
    }
}

// ---------------- launch ----------------
extern "C" void kernel_launch(void* const* d_in, const int* in_sizes, int n_in,
                              void* d_out, int out_size)
{
    const float* x     = (const float*)d_in[0];
    const float* Wq    = (const float*)d_in[1];
    const float* bq    = (const float*)d_in[2];
    const float* Wk    = (const float*)d_in[3];
    const float* bk    = (const float*)d_in[4];
    const float* Wv    = (const float*)d_in[5];
    const float* bv    = (const float*)d_in[6];
    const float* ln1_g = (const float*)d_in[7];
    const float* ln1_b = (const float*)d_in[8];
    const float* ln2_g = (const float*)d_in[9];
    const float* ln2_b = (const float*)d_in[10];
    const float* W1    = (const float*)d_in[11];
    const float* b1    = (const float*)d_in[12];
    const float* W2    = (const float*)d_in[13];
    const float* b2    = (const float*)d_in[14];
    float* out = (float*)d_out;

    uint16_t *hHi, *hLo, *h2Hi, *h2Lo, *m1Hi, *m1Lo;
    uint16_t *WqkvHi, *WqkvLo, *W1Hi, *W1Lo, *W2Hi, *W2Lo;
    float *qkv, *xmid, *bqkv;
    float2 *Qhat, *Mhat;
    cudaGetSymbolAddress((void**)&hHi,   g_h_hi);
    cudaGetSymbolAddress((void**)&hLo,   g_h_lo);
    cudaGetSymbolAddress((void**)&h2Hi,  g_h2_hi);
    cudaGetSymbolAddress((void**)&h2Lo,  g_h2_lo);
    cudaGetSymbolAddress((void**)&m1Hi,  g_m1_hi);
    cudaGetSymbolAddress((void**)&m1Lo,  g_m1_lo);
    cudaGetSymbolAddress((void**)&WqkvHi, g_Wqkv_hi);
    cudaGetSymbolAddress((void**)&WqkvLo, g_Wqkv_lo);
    cudaGetSymbolAddress((void**)&W1Hi,  g_W1_hi);
    cudaGetSymbolAddress((void**)&W1Lo,  g_W1_lo);
    cudaGetSymbolAddress((void**)&W2Hi,  g_W2_hi);
    cudaGetSymbolAddress((void**)&W2Lo,  g_W2_lo);
    cudaGetSymbolAddress((void**)&qkv,   g_qkv);
    cudaGetSymbolAddress((void**)&xmid,  g_xmid);
    cudaGetSymbolAddress((void**)&bqkv,  g_bqkv);
    cudaGetSymbolAddress((void**)&Qhat,  g_Qhat);
    cudaGetSymbolAddress((void**)&Mhat,  g_Mhat);

    cudaFuncSetAttribute(mma_gemm<0>, cudaFuncAttributeMaxDynamicSharedMemorySize, SMEM_GEMM);
    cudaFuncSetAttribute(mma_gemm<1>, cudaFuncAttributeMaxDynamicSharedMemorySize, SMEM_GEMM);
    cudaFuncSetAttribute(mma_gemm<2>, cudaFuncAttributeMaxDynamicSharedMemorySize, SMEM_GEMM);

    init_tw_kernel<<<1, 512>>>();
    bias_concat_kernel<<<NQKV / 256, 256>>>(bq, bk, bv);

    // weights -> transposed bf16 hi/lo planes
    transpose_split_kernel<<<dim3(32, 32), dim3(32, 8)>>>(Wq, WqkvHi, WqkvLo, DIM, DIM);
    transpose_split_kernel<<<dim3(32, 32), dim3(32, 8)>>>(Wk, WqkvHi + (size_t)1024 * DIM, WqkvLo + (size_t)1024 * DIM, DIM, DIM);
    transpose_split_kernel<<<dim3(32, 32), dim3(32, 8)>>>(Wv, WqkvHi + (size_t)2048 * DIM, WqkvLo + (size_t)2048 * DIM, DIM, DIM);
    transpose_split_kernel<<<dim3(128, 32), dim3(32, 8)>>>(W1, W1Hi, W1Lo, DIM, HID);
    transpose_split_kernel<<<dim3(32, 128), dim3(32, 8)>>>(W2, W2Hi, W2Lo, HID, DIM);

    // LN1 -> h planes
    ln_split_kernel<<<NROW, 256>>>(x, ln1_g, ln1_b, hHi, hLo);

    // fused QKV projection
    mma_gemm<0><<<dim3(NQKV / 128, NROW / 128), 128, SMEM_GEMM>>>(
        hHi, hLo, WqkvHi, WqkvLo, bqkv, nullptr, qkv, nullptr, nullptr, NQKV, DIM);

    // FFT + unit-magnitude normalization
    fft_norm_kernel<<<NROW, 256>>>(qkv, NQKV, 0,    Qhat, 0);
    fft_norm_kernel<<<NROW, 256>>>(qkv, NQKV, 1024, Mhat, 0);
    fft_norm_kernel<<<NROW, 256>>>(qkv, NQKV, 2048, Mhat, 1);

    // causal cumsum in Fourier domain, fused * conj(Q̂)
    chain_partial_kernel<<<(NBATCH * CHUNKS * DIM) / 256, 256>>>();
    chain_apply_kernel<<<(NBATCH * CHUNKS * DIM) / 256, 256>>>();

    // inverse FFT + residual + LN2 (emits xmid fp32 + h2 planes)
    ifft_res_ln_split_kernel<<<NROW, 256>>>(x, ln2_g, ln2_b, h2Hi, h2Lo);

    // MLP
    mma_gemm<1><<<dim3(HID / 128, NROW / 128), 128, SMEM_GEMM>>>(
        h2Hi, h2Lo, W1Hi, W1Lo, b1, nullptr, nullptr,
        (uint32_t*)m1Hi, (uint32_t*)m1Lo, HID, DIM);
    mma_gemm<2><<<dim3(DIM / 128, NROW / 128), 128, SMEM_GEMM>>>(
        m1Hi, m1Lo, W2Hi, W2Lo, b2, xmid, out, nullptr, nullptr, DIM, HID);

    (void)in_sizes; (void)n_in; (void)out_size;
}